// round 15
// baseline (speedup 1.0000x reference)
#include <cuda_runtime.h>
#include <cstdint>

#define Bsz  8192
#define INs  1024
#define H1s  2048
#define H2s  2048
#define OUTs 1024
#define Pex  8

// Scratch (device globals: allocation-free per harness rules)
__device__ float g_h1[(size_t)Bsz * H1s];            // 64 MB (relu+tf32-rounded)
__device__ float g_h2[(size_t)Bsz * H2s];            // 64 MB (relu+tf32-rounded)
__device__ float g_p1[(size_t)Bsz * Pex];
__device__ float g_p2[(size_t)Bsz * Pex];
__device__ float g_xr[(size_t)Bsz * INs];            // 32 MB (tf32-rounded x)
__device__ float g_w1t[(size_t)H1s * Pex * INs];     // 64 MB  W1^T [H1][P*IN]
__device__ float g_w2t[(size_t)H2s * Pex * H1s];     // 128 MB W2^T [H2][P*H1]
__device__ float g_wct[(size_t)OUTs * H2s];          // 8 MB   Wc^T [OUT][H2]

// ------------------------------ helpers ---------------------------------
__device__ __forceinline__ uint32_t smem_u32(const void* p) {
  uint32_t a;
  asm("{ .reg .u64 t; cvta.to.shared.u64 t, %1; cvt.u32.u64 %0, t; }"
      : "=r"(a) : "l"(p));
  return a;
}
__device__ __forceinline__ void cpa16(uint32_t s, const void* g) {
  asm volatile("cp.async.cg.shared.global [%0], [%1], 16;" :: "r"(s), "l"(g));
}
__device__ __forceinline__ void cpa_commit() {
  asm volatile("cp.async.commit_group;" ::: "memory");
}
template <int N>
__device__ __forceinline__ void cpa_wait() {
  asm volatile("cp.async.wait_group %0;" :: "n"(N) : "memory");
}
__device__ __forceinline__ uint32_t f2tf32(float f) {
  uint32_t u;
  asm("cvt.rna.tf32.f32 %0, %1;" : "=r"(u) : "f"(f));
  return u;
}
__device__ __forceinline__ float rtf(float f) {
  return __uint_as_float(f2tf32(f));
}
__device__ __forceinline__ void ldsm4(uint32_t (&r)[4], uint32_t a) {
  asm volatile("ldmatrix.sync.aligned.m8n8.x4.shared.b16 {%0,%1,%2,%3}, [%4];"
               : "=r"(r[0]), "=r"(r[1]), "=r"(r[2]), "=r"(r[3]) : "r"(a));
}
__device__ __forceinline__ void mma_t(float (&c)[4], const uint32_t (&a)[4],
                                      uint32_t b0, uint32_t b1) {
  asm volatile(
      "mma.sync.aligned.m16n8k8.row.col.f32.tf32.tf32.f32 "
      "{%0,%1,%2,%3}, {%4,%5,%6,%7}, {%8,%9}, {%0,%1,%2,%3};"
      : "+f"(c[0]), "+f"(c[1]), "+f"(c[2]), "+f"(c[3])
      : "r"(a[0]), "r"(a[1]), "r"(a[2]), "r"(a[3]), "r"(b0), "r"(b1));
}

// -------------------------------------------------------------------------
// Body: tf32 pre-round (x). One block = 256 float4s at block index b.
// -------------------------------------------------------------------------
__device__ __forceinline__ void round_body(int b,
                                           const float4* __restrict__ in,
                                           float4* __restrict__ out, int n4) {
  int i = b * 256 + threadIdx.x;
  if (i < n4) {
    float4 v = in[i];
    v.x = rtf(v.x); v.y = rtf(v.y); v.z = rtf(v.z); v.w = rtf(v.w);
    out[i] = v;
  }
}

// -------------------------------------------------------------------------
// Body: vectorized transpose + tf32-round: out[n*K + k] = rna(in[k*N + n]).
// Tile 32(k) x 128(n), 256 threads, float4 gmem both sides. (R10-validated.)
// -------------------------------------------------------------------------
__device__ __forceinline__ void transpose_body(float4 (*t4)[32],
                                               int bkx, int bny,
                                               const float4* __restrict__ in4,
                                               float4* __restrict__ out4,
                                               int K, int N) {
  const int tid = threadIdx.x;
  const int k0 = bkx * 32, n0 = bny * 128;
  const int N4 = N >> 2, K4 = K >> 2;

#pragma unroll
  for (int r = 0; r < 4; r++) {
    int idx = tid + r * 256;
    int k = idx >> 5, nc = idx & 31;
    t4[k][nc ^ ((k >> 2) & 7)] =
        in4[(size_t)(k0 + k) * N4 + (n0 >> 2) + nc];
  }
  __syncthreads();

  const int kb = tid & 7, nb = tid >> 3;
  float4 r0 = t4[4 * kb + 0][nb ^ kb];
  float4 r1 = t4[4 * kb + 1][nb ^ kb];
  float4 r2 = t4[4 * kb + 2][nb ^ kb];
  float4 r3 = t4[4 * kb + 3][nb ^ kb];

  size_t ob = (size_t)(n0 + 4 * nb) * K4 + (k0 >> 2) + kb;
  float4 o;
  o.x = rtf(r0.x); o.y = rtf(r1.x); o.z = rtf(r2.x); o.w = rtf(r3.x);
  out4[ob] = o;
  o.x = rtf(r0.y); o.y = rtf(r1.y); o.z = rtf(r2.y); o.w = rtf(r3.y);
  out4[ob + K4] = o;
  o.x = rtf(r0.z); o.y = rtf(r1.z); o.z = rtf(r2.z); o.w = rtf(r3.z);
  out4[ob + 2 * (size_t)K4] = o;
  o.x = rtf(r0.w); o.y = rtf(r1.w); o.z = rtf(r2.w); o.w = rtf(r3.w);
  out4[ob + 3 * (size_t)K4] = o;
}

// -------------------------------------------------------------------------
// Body: selector probs = softmax(X @ S + sb). Block b = 8 warps x 4 rows.
// -------------------------------------------------------------------------
__device__ __forceinline__ void selector_body(int b,
                                              const float* __restrict__ X,
                                              const float* __restrict__ S,
                                              const float* __restrict__ sb,
                                              float* __restrict__ probs,
                                              int K) {
  int gw = b * 8 + (threadIdx.x >> 5);
  int lane = threadIdx.x & 31;
  int row0 = gw * 4;
  int nvec = K >> 2;

  float acc[4][8];
#pragma unroll
  for (int r = 0; r < 4; r++)
#pragma unroll
    for (int p = 0; p < 8; p++) acc[r][p] = 0.f;

  for (int v = lane; v < nvec; v += 32) {
    const float4* Sv = reinterpret_cast<const float4*>(S + ((size_t)v << 2) * 8);
    float4 s0 = Sv[0], s1 = Sv[1], s2 = Sv[2], s3 = Sv[3];
    float4 s4 = Sv[4], s5 = Sv[5], s6 = Sv[6], s7 = Sv[7];
#pragma unroll
    for (int r = 0; r < 4; r++) {
      float4 x4 = reinterpret_cast<const float4*>(X + (size_t)(row0 + r) * K)[v];
      acc[r][0] += x4.x * s0.x + x4.y * s2.x + x4.z * s4.x + x4.w * s6.x;
      acc[r][1] += x4.x * s0.y + x4.y * s2.y + x4.z * s4.y + x4.w * s6.y;
      acc[r][2] += x4.x * s0.z + x4.y * s2.z + x4.z * s4.z + x4.w * s6.z;
      acc[r][3] += x4.x * s0.w + x4.y * s2.w + x4.z * s4.w + x4.w * s6.w;
      acc[r][4] += x4.x * s1.x + x4.y * s3.x + x4.z * s5.x + x4.w * s7.x;
      acc[r][5] += x4.x * s1.y + x4.y * s3.y + x4.z * s5.y + x4.w * s7.y;
      acc[r][6] += x4.x * s1.z + x4.y * s3.z + x4.z * s5.z + x4.w * s7.z;
      acc[r][7] += x4.x * s1.w + x4.y * s3.w + x4.z * s5.w + x4.w * s7.w;
    }
  }
#pragma unroll
  for (int off = 16; off; off >>= 1)
#pragma unroll
    for (int r = 0; r < 4; r++)
#pragma unroll
      for (int p = 0; p < 8; p++)
        acc[r][p] += __shfl_xor_sync(0xffffffffu, acc[r][p], off);

  if (lane < 4) {
    int r = lane;
    float a[8];
    float m = -1e30f;
#pragma unroll
    for (int p = 0; p < 8; p++) { a[p] = acc[r][p] + sb[p]; m = fmaxf(m, a[p]); }
    float s = 0.f;
#pragma unroll
    for (int p = 0; p < 8; p++) { a[p] = __expf(a[p] - m); s += a[p]; }
    float inv = 1.f / s;
#pragma unroll
    for (int p = 0; p < 8; p++) probs[(size_t)(row0 + r) * 8 + p] = a[p] * inv;
  }
}

// -------------------------------------------------------------------------
// Standalone selector kernel (layer 2 — depends on h1).
// -------------------------------------------------------------------------
__global__ void selector_kernel(const float* __restrict__ X,
                                const float* __restrict__ S,
                                const float* __restrict__ sb,
                                float* __restrict__ probs, int K) {
  selector_body(blockIdx.x, X, S, sb, probs, K);
}

// -------------------------------------------------------------------------
// Fused prep kernel: selector1 + x round + W1/W2/Wc transposes, all
// independent, dispatched by flat block ranges (identical per-block work to
// the previous 5 separate launches).
//   [0, 256)            selector1            (Bsz/32 blocks)
//   [256, 8448)         x round              (8192 blocks)
//   [8448, 12544)       W1^T  (256 x 16)     (4096 blocks)
//   [12544, 20736)      W2^T  (512 x 16)     (8192 blocks)
//   [20736, 21248)      Wc^T  (64 x 8)       (512 blocks)
// -------------------------------------------------------------------------
__global__ void prep_kernel(const float* __restrict__ x,
                            const float* __restrict__ S1,
                            const float* __restrict__ sb1,
                            float* __restrict__ p1, float* __restrict__ xr,
                            const float* __restrict__ W1,
                            float* __restrict__ w1t,
                            const float* __restrict__ W2,
                            float* __restrict__ w2t,
                            const float* __restrict__ Wc,
                            float* __restrict__ wct) {
  __shared__ float4 t4[32][32];
  int b = blockIdx.x;
  if (b < 256) {
    selector_body(b, x, S1, sb1, p1, INs);
    return;
  }
  b -= 256;
  if (b < 8192) {
    round_body(b, (const float4*)x, (float4*)xr, (Bsz * INs) / 4);
    return;
  }
  b -= 8192;
  if (b < 4096) {
    transpose_body(t4, b & 255, b >> 8, (const float4*)W1, (float4*)w1t,
                   Pex * INs, H1s);
    return;
  }
  b -= 4096;
  if (b < 8192) {
    transpose_body(t4, b & 511, b >> 9, (const float4*)W2, (float4*)w2t,
                   Pex * H1s, H2s);
    return;
  }
  b -= 8192;
  transpose_body(t4, b & 63, b >> 6, (const float4*)Wc, (float4*)wct,
                 H2s, OUTs);
}
#define PREP_BLOCKS (256 + 8192 + 4096 + 8192 + 512)

// -------------------------------------------------------------------------
// mma.sync tf32 GEMM, CTA tile 128x128x32, 128 threads (4 warps x 64x64),
// 3-stage cp.async, 2 CTAs/SM. Both operands via ldmatrix (B = W^T).
//   MOE: probs via accumulator rescale at expert boundaries.
//   RR : relu + tf32-round at store (hidden layers).
// (R11 configuration — measured best, unchanged.)
// -------------------------------------------------------------------------
template <bool MOE, bool RR, int LOG_IN>
__global__ __launch_bounds__(128, 2) void tc_gemm(
    int N, int K,
    const float* __restrict__ X, const float* __restrict__ Wt,
    const float* __restrict__ probs, const float* __restrict__ bias,
    float* __restrict__ C) {
  constexpr int NST = 3;
  constexpr int STAGE_B = 32768;                 // A 16KB + B 16KB
  constexpr int LDA = 1 << LOG_IN;
  constexpr int MASK = LDA - 1;
  constexpr int CPE = LDA / 32;                  // chunks per expert

  extern __shared__ float smf[];
  __shared__ float probs_s[128][8];
  __shared__ float bias_s[8][128];

  const int tid = threadIdx.x, lane = tid & 31, wid = tid >> 5;
  const int wm = wid >> 1, wn = wid & 1;         // 2x2 warp grid, 64x64 tiles
  const int m0 = blockIdx.y * 128, n0 = blockIdx.x * 128;
  const uint32_t sbase = smem_u32(smf);

  if (MOE) {
    for (int i = tid; i < 1024; i += 128) {
      int r = i >> 3, p = i & 7;
      probs_s[r][p] = probs[(size_t)(m0 + r) * 8 + p];
    }
    for (int i = tid; i < 1024; i += 128) {
      int p = i >> 7, c = i & 127;
      bias_s[p][c] = bias[(size_t)p * N + n0 + c];
    }
  } else {
    bias_s[0][tid] = bias[n0 + tid];
  }

  const int nchunk = K >> 5;

  auto issue = [&](int c, int st) {
    const int k0 = c << 5;
    const uint32_t sA = sbase + (uint32_t)st * STAGE_B;
    const uint32_t sB = sA + 16384;
    const float* ab = X + (k0 & MASK);
#pragma unroll
    for (int i = 0; i < 8; i++) {            // A: 128 m-rows x 32 k, SW128
      int f = tid + i * 128;
      int m = f >> 3, g = f & 7;
      cpa16(sA + (uint32_t)(m * 128 + ((g ^ (m & 7)) << 4)),
            ab + (size_t)(m0 + m) * LDA + g * 4);
    }
#pragma unroll
    for (int i = 0; i < 8; i++) {            // B: 128 n-rows x 32 k, SW128
      int f = tid + i * 128;
      int n = f >> 3, g = f & 7;
      cpa16(sB + (uint32_t)(n * 128 + ((g ^ (n & 7)) << 4)),
            Wt + (size_t)(n0 + n) * K + k0 + g * 4);
    }
    cpa_commit();
  };

  float cacc[4][8][4];
#pragma unroll
  for (int a = 0; a < 4; a++)
#pragma unroll
    for (int b = 0; b < 8; b++)
#pragma unroll
      for (int d = 0; d < 4; d++) cacc[a][b][d] = 0.f;

  // ldmatrix per-thread address components (A: m rows; B: n rows)
  const int q = lane >> 3, r8v = lane & 7, qh = q >> 1;
  uint32_t arow[4]; int arow7[4];
#pragma unroll
  for (int mt = 0; mt < 4; mt++) {
    int r = wm * 64 + mt * 16 + (q & 1) * 8 + r8v;
    arow[mt] = (uint32_t)r * 128u;
    arow7[mt] = r & 7;
  }
  uint32_t brow[4]; int brow7[4];
#pragma unroll
  for (int nb = 0; nb < 4; nb++) {
    int r = wn * 64 + nb * 16 + (q & 1) * 8 + r8v;
    brow[nb] = (uint32_t)r * 128u;
    brow7[nb] = r & 7;
  }
  const int grp = lane >> 2, tig = lane & 3;

  float pr_lo[4], pr_hi[4];

  issue(0, 0);
  issue(1, 1);

  int st = 0;
  for (int c = 0; c < nchunk; c++) {
    cpa_wait<1>();
    __syncthreads();
    {
      int cn = c + 2;
      if (cn < nchunk) {
        int stn = st + 2; if (stn >= NST) stn -= NST;
        issue(cn, stn);
      } else {
        cpa_commit();
      }
    }

    if (MOE && (c & (CPE - 1)) == 0) {
      // expert boundary: rescale accumulator by pr_old/pr_new (registers only)
      const int p = c >> (LOG_IN - 5);
#pragma unroll
      for (int mt = 0; mt < 4; mt++) {
        int r = wm * 64 + mt * 16 + grp;
        float nlo = probs_s[r][p], nhi = probs_s[r + 8][p];
        if (c) {
          float rlo = pr_lo[mt] / nlo, rhi = pr_hi[mt] / nhi;
#pragma unroll
          for (int nt = 0; nt < 8; nt++) {
            cacc[mt][nt][0] *= rlo; cacc[mt][nt][1] *= rlo;
            cacc[mt][nt][2] *= rhi; cacc[mt][nt][3] *= rhi;
          }
        }
        pr_lo[mt] = nlo; pr_hi[mt] = nhi;
      }
    }

    const uint32_t sA = sbase + (uint32_t)st * STAGE_B;
    const uint32_t sB = sA + 16384;
#pragma unroll
    for (int ks = 0; ks < 4; ks++) {
      uint32_t af[4][4];
#pragma unroll
      for (int mt = 0; mt < 4; mt++)
        ldsm4(af[mt], sA + arow[mt] +
                          (uint32_t)(((ks * 2 + qh) ^ arow7[mt]) << 4));
      uint32_t bfr[4][4];
#pragma unroll
      for (int nb = 0; nb < 4; nb++)
        ldsm4(bfr[nb], sB + brow[nb] +
                           (uint32_t)(((ks * 2 + qh) ^ brow7[nb]) << 4));
#pragma unroll
      for (int mt = 0; mt < 4; mt++)
#pragma unroll
        for (int nb = 0; nb < 4; nb++) {
          mma_t(cacc[mt][2 * nb + 0], af[mt], bfr[nb][0], bfr[nb][2]);
          mma_t(cacc[mt][2 * nb + 1], af[mt], bfr[nb][1], bfr[nb][3]);
        }
    }
    st++; if (st >= NST) st = 0;
  }

  if (MOE) {
    // final scale by pr_last
#pragma unroll
    for (int mt = 0; mt < 4; mt++)
#pragma unroll
      for (int nt = 0; nt < 8; nt++) {
        cacc[mt][nt][0] *= pr_lo[mt]; cacc[mt][nt][1] *= pr_lo[mt];
        cacc[mt][nt][2] *= pr_hi[mt]; cacc[mt][nt][3] *= pr_hi[mt];
      }
  }

  // ---- epilogue ----
#pragma unroll
  for (int mt = 0; mt < 4; mt++) {
#pragma unroll
    for (int half = 0; half < 2; half++) {
      int r = wm * 64 + mt * 16 + grp + half * 8;
      int m = m0 + r;
      float prr[8];
      if (MOE) {
#pragma unroll
        for (int p = 0; p < 8; p++) prr[p] = probs_s[r][p];
      }
#pragma unroll
      for (int nt = 0; nt < 8; nt++) {
        int nloc = wn * 64 + nt * 8 + tig * 2;
        float v0 = cacc[mt][nt][half * 2 + 0];
        float v1 = cacc[mt][nt][half * 2 + 1];
        if (MOE) {
          float cb0 = 0.f, cb1 = 0.f;
#pragma unroll
          for (int p = 0; p < 8; p++) {
            cb0 += prr[p] * bias_s[p][nloc];
            cb1 += prr[p] * bias_s[p][nloc + 1];
          }
          v0 += cb0; v1 += cb1;
        } else {
          v0 += bias_s[0][nloc];
          v1 += bias_s[0][nloc + 1];
        }
        if (RR) {
          v0 = rtf(fmaxf(v0, 0.f));
          v1 = rtf(fmaxf(v1, 0.f));
        }
        float2 o; o.x = v0; o.y = v1;
        *reinterpret_cast<float2*>(&C[(size_t)m * N + n0 + nloc]) = o;
      }
    }
  }
}

// -------------------------------------------------------------------------
extern "C" void kernel_launch(void* const* d_in, const int* in_sizes, int n_in,
                              void* d_out, int out_size) {
  const float* x   = (const float*)d_in[0];
  const float* W1  = (const float*)d_in[1];
  const float* b1  = (const float*)d_in[2];
  const float* S1  = (const float*)d_in[3];
  const float* sb1 = (const float*)d_in[4];
  const float* W2  = (const float*)d_in[5];
  const float* b2  = (const float*)d_in[6];
  const float* S2  = (const float*)d_in[7];
  const float* sb2 = (const float*)d_in[8];
  const float* Wc  = (const float*)d_in[9];
  const float* bc  = (const float*)d_in[10];
  float* out = (float*)d_out;

  float *h1, *h2, *p1, *p2, *xr, *w1t, *w2t, *wct;
  cudaGetSymbolAddress((void**)&h1, g_h1);
  cudaGetSymbolAddress((void**)&h2, g_h2);
  cudaGetSymbolAddress((void**)&p1, g_p1);
  cudaGetSymbolAddress((void**)&p2, g_p2);
  cudaGetSymbolAddress((void**)&xr, g_xr);
  cudaGetSymbolAddress((void**)&w1t, g_w1t);
  cudaGetSymbolAddress((void**)&w2t, g_w2t);
  cudaGetSymbolAddress((void**)&wct, g_wct);

  const int SMEM_DYN = 3 * 32768;   // 98304 B -> 2 CTAs/SM
  cudaFuncSetAttribute(tc_gemm<true, true, 10>,
                       cudaFuncAttributeMaxDynamicSharedMemorySize, SMEM_DYN);
  cudaFuncSetAttribute(tc_gemm<true, true, 11>,
                       cudaFuncAttributeMaxDynamicSharedMemorySize, SMEM_DYN);
  cudaFuncSetAttribute(tc_gemm<false, false, 11>,
                       cudaFuncAttributeMaxDynamicSharedMemorySize, SMEM_DYN);

  // fused prep: selector1 + x round + W1/W2/Wc transpose+round, one launch
  prep_kernel<<<PREP_BLOCKS, 256>>>(x, S1, sb1, p1, xr,
                                    W1, w1t, W2, w2t, Wc, wct);

  // ---- layer 1 ----
  tc_gemm<true, true, 10><<<dim3(H1s / 128, Bsz / 128), 128, SMEM_DYN>>>(
      H1s, Pex * INs, xr, w1t, p1, b1, h1);

  // ---- layer 2 ----
  selector_kernel<<<Bsz / 32, 256>>>(h1, S2, sb2, p2, H1s);
  tc_gemm<true, true, 11><<<dim3(H2s / 128, Bsz / 128), 128, SMEM_DYN>>>(
      H2s, Pex * H1s, h1, w2t, p2, b2, h2);

  // ---- classifier ----
  tc_gemm<false, false, 11><<<dim3(OUTs / 128, Bsz / 128), 128, SMEM_DYN>>>(
      OUTs, H2s, h2, wct, nullptr, bc, out);
}

// round 16
// speedup vs baseline: 1.0038x; 1.0038x over previous
#include <cuda_runtime.h>
#include <cstdint>

#define Bsz  8192
#define INs  1024
#define H1s  2048
#define H2s  2048
#define OUTs 1024
#define Pex  8

// Scratch (device globals: allocation-free per harness rules)
__device__ float g_h1[(size_t)Bsz * H1s];            // 64 MB (relu+tf32-rounded)
__device__ float g_h2[(size_t)Bsz * H2s];            // 64 MB (relu+tf32-rounded)
__device__ float g_p1[(size_t)Bsz * Pex];
__device__ float g_p2[(size_t)Bsz * Pex];
__device__ float g_xr[(size_t)Bsz * INs];            // 32 MB (tf32-rounded x)
__device__ float g_w1t[(size_t)H1s * Pex * INs];     // 64 MB  W1^T [H1][P*IN]
__device__ float g_w2t[(size_t)H2s * Pex * H1s];     // 128 MB W2^T [H2][P*H1]
__device__ float g_wct[(size_t)OUTs * H2s];          // 8 MB   Wc^T [OUT][H2]

// ------------------------------ helpers ---------------------------------
__device__ __forceinline__ uint32_t smem_u32(const void* p) {
  uint32_t a;
  asm("{ .reg .u64 t; cvta.to.shared.u64 t, %1; cvt.u32.u64 %0, t; }"
      : "=r"(a) : "l"(p));
  return a;
}
__device__ __forceinline__ void cpa16(uint32_t s, const void* g) {
  asm volatile("cp.async.cg.shared.global [%0], [%1], 16;" :: "r"(s), "l"(g));
}
__device__ __forceinline__ void cpa_commit() {
  asm volatile("cp.async.commit_group;" ::: "memory");
}
template <int N>
__device__ __forceinline__ void cpa_wait() {
  asm volatile("cp.async.wait_group %0;" :: "n"(N) : "memory");
}
__device__ __forceinline__ uint32_t f2tf32(float f) {
  uint32_t u;
  asm("cvt.rna.tf32.f32 %0, %1;" : "=r"(u) : "f"(f));
  return u;
}
__device__ __forceinline__ float rtf(float f) {
  return __uint_as_float(f2tf32(f));
}
__device__ __forceinline__ void ldsm4(uint32_t (&r)[4], uint32_t a) {
  asm volatile("ldmatrix.sync.aligned.m8n8.x4.shared.b16 {%0,%1,%2,%3}, [%4];"
               : "=r"(r[0]), "=r"(r[1]), "=r"(r[2]), "=r"(r[3]) : "r"(a));
}
__device__ __forceinline__ void mma_t(float (&c)[4], const uint32_t (&a)[4],
                                      uint32_t b0, uint32_t b1) {
  asm volatile(
      "mma.sync.aligned.m16n8k8.row.col.f32.tf32.tf32.f32 "
      "{%0,%1,%2,%3}, {%4,%5,%6,%7}, {%8,%9}, {%0,%1,%2,%3};"
      : "+f"(c[0]), "+f"(c[1]), "+f"(c[2]), "+f"(c[3])
      : "r"(a[0]), "r"(a[1]), "r"(a[2]), "r"(a[3]), "r"(b0), "r"(b1));
}

// -------------------------------------------------------------------------
// tf32 pre-round (x)
// -------------------------------------------------------------------------
__global__ void round_tf32_kernel(const float4* __restrict__ in,
                                  float4* __restrict__ out, int n4) {
  int i = blockIdx.x * blockDim.x + threadIdx.x;
  if (i < n4) {
    float4 v = in[i];
    v.x = rtf(v.x); v.y = rtf(v.y); v.z = rtf(v.z); v.w = rtf(v.w);
    out[i] = v;
  }
}

// -------------------------------------------------------------------------
// Vectorized transpose + tf32-round: out[n*K + k] = rna(in[k*N + n]).
// Tile 32(k) x 128(n), 256 threads, float4 gmem both sides.
// -------------------------------------------------------------------------
__global__ void transpose_round_kernel(const float4* __restrict__ in4,
                                       float4* __restrict__ out4,
                                       int K, int N) {
  __shared__ float4 t4[32][32];
  const int tid = threadIdx.x;
  const int k0 = blockIdx.x * 32, n0 = blockIdx.y * 128;
  const int N4 = N >> 2, K4 = K >> 2;

#pragma unroll
  for (int r = 0; r < 4; r++) {
    int idx = tid + r * 256;
    int k = idx >> 5, nc = idx & 31;
    t4[k][nc ^ ((k >> 2) & 7)] =
        in4[(size_t)(k0 + k) * N4 + (n0 >> 2) + nc];
  }
  __syncthreads();

  const int kb = tid & 7, nb = tid >> 3;
  float4 r0 = t4[4 * kb + 0][nb ^ kb];
  float4 r1 = t4[4 * kb + 1][nb ^ kb];
  float4 r2 = t4[4 * kb + 2][nb ^ kb];
  float4 r3 = t4[4 * kb + 3][nb ^ kb];

  size_t ob = (size_t)(n0 + 4 * nb) * K4 + (k0 >> 2) + kb;
  float4 o;
  o.x = rtf(r0.x); o.y = rtf(r1.x); o.z = rtf(r2.x); o.w = rtf(r3.x);
  out4[ob] = o;
  o.x = rtf(r0.y); o.y = rtf(r1.y); o.z = rtf(r2.y); o.w = rtf(r3.y);
  out4[ob + K4] = o;
  o.x = rtf(r0.z); o.y = rtf(r1.z); o.z = rtf(r2.z); o.w = rtf(r3.z);
  out4[ob + 2 * (size_t)K4] = o;
  o.x = rtf(r0.w); o.y = rtf(r1.w); o.z = rtf(r2.w); o.w = rtf(r3.w);
  out4[ob + 3 * (size_t)K4] = o;
}

// -------------------------------------------------------------------------
// Selector: probs = softmax(X @ S + sb). One warp per 4 rows (S reused).
// -------------------------------------------------------------------------
__global__ void selector_kernel(const float* __restrict__ X,
                                const float* __restrict__ S,
                                const float* __restrict__ sb,
                                float* __restrict__ probs, int K) {
  int gw = (blockIdx.x * blockDim.x + threadIdx.x) >> 5;
  int lane = threadIdx.x & 31;
  int row0 = gw * 4;
  int nvec = K >> 2;

  float acc[4][8];
#pragma unroll
  for (int r = 0; r < 4; r++)
#pragma unroll
    for (int p = 0; p < 8; p++) acc[r][p] = 0.f;

  for (int v = lane; v < nvec; v += 32) {
    const float4* Sv = reinterpret_cast<const float4*>(S + ((size_t)v << 2) * 8);
    float4 s0 = Sv[0], s1 = Sv[1], s2 = Sv[2], s3 = Sv[3];
    float4 s4 = Sv[4], s5 = Sv[5], s6 = Sv[6], s7 = Sv[7];
#pragma unroll
    for (int r = 0; r < 4; r++) {
      float4 x4 = reinterpret_cast<const float4*>(X + (size_t)(row0 + r) * K)[v];
      acc[r][0] += x4.x * s0.x + x4.y * s2.x + x4.z * s4.x + x4.w * s6.x;
      acc[r][1] += x4.x * s0.y + x4.y * s2.y + x4.z * s4.y + x4.w * s6.y;
      acc[r][2] += x4.x * s0.z + x4.y * s2.z + x4.z * s4.z + x4.w * s6.z;
      acc[r][3] += x4.x * s0.w + x4.y * s2.w + x4.z * s4.w + x4.w * s6.w;
      acc[r][4] += x4.x * s1.x + x4.y * s3.x + x4.z * s5.x + x4.w * s7.x;
      acc[r][5] += x4.x * s1.y + x4.y * s3.y + x4.z * s5.y + x4.w * s7.y;
      acc[r][6] += x4.x * s1.z + x4.y * s3.z + x4.z * s5.z + x4.w * s7.z;
      acc[r][7] += x4.x * s1.w + x4.y * s3.w + x4.z * s5.w + x4.w * s7.w;
    }
  }
#pragma unroll
  for (int off = 16; off; off >>= 1)
#pragma unroll
    for (int r = 0; r < 4; r++)
#pragma unroll
      for (int p = 0; p < 8; p++)
        acc[r][p] += __shfl_xor_sync(0xffffffffu, acc[r][p], off);

  if (lane < 4) {
    int r = lane;
    float a[8];
    float m = -1e30f;
#pragma unroll
    for (int p = 0; p < 8; p++) { a[p] = acc[r][p] + sb[p]; m = fmaxf(m, a[p]); }
    float s = 0.f;
#pragma unroll
    for (int p = 0; p < 8; p++) { a[p] = __expf(a[p] - m); s += a[p]; }
    float inv = 1.f / s;
#pragma unroll
    for (int p = 0; p < 8; p++) probs[(size_t)(row0 + r) * 8 + p] = a[p] * inv;
  }
}

// -------------------------------------------------------------------------
// mma.sync tf32 GEMM, CTA tile 128x128x32, 128 threads (4 warps x 64x64),
// 3-stage cp.async, 2 CTAs/SM. Both operands via ldmatrix (B = W^T).
//   MOE: probs via accumulator rescale at expert boundaries.
//   RR : relu + tf32-round at store (hidden layers).
// (R11 configuration — measured best: 4424.5 / 4428.6 us.)
// -------------------------------------------------------------------------
template <bool MOE, bool RR, int LOG_IN>
__global__ __launch_bounds__(128, 2) void tc_gemm(
    int N, int K,
    const float* __restrict__ X, const float* __restrict__ Wt,
    const float* __restrict__ probs, const float* __restrict__ bias,
    float* __restrict__ C) {
  constexpr int NST = 3;
  constexpr int STAGE_B = 32768;                 // A 16KB + B 16KB
  constexpr int LDA = 1 << LOG_IN;
  constexpr int MASK = LDA - 1;
  constexpr int CPE = LDA / 32;                  // chunks per expert

  extern __shared__ float smf[];
  __shared__ float probs_s[128][8];
  __shared__ float bias_s[8][128];

  const int tid = threadIdx.x, lane = tid & 31, wid = tid >> 5;
  const int wm = wid >> 1, wn = wid & 1;         // 2x2 warp grid, 64x64 tiles
  const int m0 = blockIdx.y * 128, n0 = blockIdx.x * 128;
  const uint32_t sbase = smem_u32(smf);

  if (MOE) {
    for (int i = tid; i < 1024; i += 128) {
      int r = i >> 3, p = i & 7;
      probs_s[r][p] = probs[(size_t)(m0 + r) * 8 + p];
    }
    for (int i = tid; i < 1024; i += 128) {
      int p = i >> 7, c = i & 127;
      bias_s[p][c] = bias[(size_t)p * N + n0 + c];
    }
  } else {
    bias_s[0][tid] = bias[n0 + tid];
  }

  const int nchunk = K >> 5;

  auto issue = [&](int c, int st) {
    const int k0 = c << 5;
    const uint32_t sA = sbase + (uint32_t)st * STAGE_B;
    const uint32_t sB = sA + 16384;
    const float* ab = X + (k0 & MASK);
#pragma unroll
    for (int i = 0; i < 8; i++) {            // A: 128 m-rows x 32 k, SW128
      int f = tid + i * 128;
      int m = f >> 3, g = f & 7;
      cpa16(sA + (uint32_t)(m * 128 + ((g ^ (m & 7)) << 4)),
            ab + (size_t)(m0 + m) * LDA + g * 4);
    }
#pragma unroll
    for (int i = 0; i < 8; i++) {            // B: 128 n-rows x 32 k, SW128
      int f = tid + i * 128;
      int n = f >> 3, g = f & 7;
      cpa16(sB + (uint32_t)(n * 128 + ((g ^ (n & 7)) << 4)),
            Wt + (size_t)(n0 + n) * K + k0 + g * 4);
    }
    cpa_commit();
  };

  float cacc[4][8][4];
#pragma unroll
  for (int a = 0; a < 4; a++)
#pragma unroll
    for (int b = 0; b < 8; b++)
#pragma unroll
      for (int d = 0; d < 4; d++) cacc[a][b][d] = 0.f;

  // ldmatrix per-thread address components (A: m rows; B: n rows)
  const int q = lane >> 3, r8v = lane & 7, qh = q >> 1;
  uint32_t arow[4]; int arow7[4];
#pragma unroll
  for (int mt = 0; mt < 4; mt++) {
    int r = wm * 64 + mt * 16 + (q & 1) * 8 + r8v;
    arow[mt] = (uint32_t)r * 128u;
    arow7[mt] = r & 7;
  }
  uint32_t brow[4]; int brow7[4];
#pragma unroll
  for (int nb = 0; nb < 4; nb++) {
    int r = wn * 64 + nb * 16 + (q & 1) * 8 + r8v;
    brow[nb] = (uint32_t)r * 128u;
    brow7[nb] = r & 7;
  }
  const int grp = lane >> 2, tig = lane & 3;

  float pr_lo[4], pr_hi[4];

  issue(0, 0);
  issue(1, 1);

  int st = 0;
  for (int c = 0; c < nchunk; c++) {
    cpa_wait<1>();
    __syncthreads();
    {
      int cn = c + 2;
      if (cn < nchunk) {
        int stn = st + 2; if (stn >= NST) stn -= NST;
        issue(cn, stn);
      } else {
        cpa_commit();
      }
    }

    if (MOE && (c & (CPE - 1)) == 0) {
      // expert boundary: rescale accumulator by pr_old/pr_new (registers only)
      const int p = c >> (LOG_IN - 5);
#pragma unroll
      for (int mt = 0; mt < 4; mt++) {
        int r = wm * 64 + mt * 16 + grp;
        float nlo = probs_s[r][p], nhi = probs_s[r + 8][p];
        if (c) {
          float rlo = pr_lo[mt] / nlo, rhi = pr_hi[mt] / nhi;
#pragma unroll
          for (int nt = 0; nt < 8; nt++) {
            cacc[mt][nt][0] *= rlo; cacc[mt][nt][1] *= rlo;
            cacc[mt][nt][2] *= rhi; cacc[mt][nt][3] *= rhi;
          }
        }
        pr_lo[mt] = nlo; pr_hi[mt] = nhi;
      }
    }

    const uint32_t sA = sbase + (uint32_t)st * STAGE_B;
    const uint32_t sB = sA + 16384;
#pragma unroll
    for (int ks = 0; ks < 4; ks++) {
      uint32_t af[4][4];
#pragma unroll
      for (int mt = 0; mt < 4; mt++)
        ldsm4(af[mt], sA + arow[mt] +
                          (uint32_t)(((ks * 2 + qh) ^ arow7[mt]) << 4));
      uint32_t bfr[4][4];
#pragma unroll
      for (int nb = 0; nb < 4; nb++)
        ldsm4(bfr[nb], sB + brow[nb] +
                           (uint32_t)(((ks * 2 + qh) ^ brow7[nb]) << 4));
#pragma unroll
      for (int mt = 0; mt < 4; mt++)
#pragma unroll
        for (int nb = 0; nb < 4; nb++) {
          mma_t(cacc[mt][2 * nb + 0], af[mt], bfr[nb][0], bfr[nb][2]);
          mma_t(cacc[mt][2 * nb + 1], af[mt], bfr[nb][1], bfr[nb][3]);
        }
    }
    st++; if (st >= NST) st = 0;
  }

  if (MOE) {
    // final scale by pr_last
#pragma unroll
    for (int mt = 0; mt < 4; mt++)
#pragma unroll
      for (int nt = 0; nt < 8; nt++) {
        cacc[mt][nt][0] *= pr_lo[mt]; cacc[mt][nt][1] *= pr_lo[mt];
        cacc[mt][nt][2] *= pr_hi[mt]; cacc[mt][nt][3] *= pr_hi[mt];
      }
  }

  // ---- epilogue ----
#pragma unroll
  for (int mt = 0; mt < 4; mt++) {
#pragma unroll
    for (int half = 0; half < 2; half++) {
      int r = wm * 64 + mt * 16 + grp + half * 8;
      int m = m0 + r;
      float prr[8];
      if (MOE) {
#pragma unroll
        for (int p = 0; p < 8; p++) prr[p] = probs_s[r][p];
      }
#pragma unroll
      for (int nt = 0; nt < 8; nt++) {
        int nloc = wn * 64 + nt * 8 + tig * 2;
        float v0 = cacc[mt][nt][half * 2 + 0];
        float v1 = cacc[mt][nt][half * 2 + 1];
        if (MOE) {
          float cb0 = 0.f, cb1 = 0.f;
#pragma unroll
          for (int p = 0; p < 8; p++) {
            cb0 += prr[p] * bias_s[p][nloc];
            cb1 += prr[p] * bias_s[p][nloc + 1];
          }
          v0 += cb0; v1 += cb1;
        } else {
          v0 += bias_s[0][nloc];
          v1 += bias_s[0][nloc + 1];
        }
        if (RR) {
          v0 = rtf(fmaxf(v0, 0.f));
          v1 = rtf(fmaxf(v1, 0.f));
        }
        float2 o; o.x = v0; o.y = v1;
        *reinterpret_cast<float2*>(&C[(size_t)m * N + n0 + nloc]) = o;
      }
    }
  }
}

// -------------------------------------------------------------------------
extern "C" void kernel_launch(void* const* d_in, const int* in_sizes, int n_in,
                              void* d_out, int out_size) {
  const float* x   = (const float*)d_in[0];
  const float* W1  = (const float*)d_in[1];
  const float* b1  = (const float*)d_in[2];
  const float* S1  = (const float*)d_in[3];
  const float* sb1 = (const float*)d_in[4];
  const float* W2  = (const float*)d_in[5];
  const float* b2  = (const float*)d_in[6];
  const float* S2  = (const float*)d_in[7];
  const float* sb2 = (const float*)d_in[8];
  const float* Wc  = (const float*)d_in[9];
  const float* bc  = (const float*)d_in[10];
  float* out = (float*)d_out;

  float *h1, *h2, *p1, *p2, *xr, *w1t, *w2t, *wct;
  cudaGetSymbolAddress((void**)&h1, g_h1);
  cudaGetSymbolAddress((void**)&h2, g_h2);
  cudaGetSymbolAddress((void**)&p1, g_p1);
  cudaGetSymbolAddress((void**)&p2, g_p2);
  cudaGetSymbolAddress((void**)&xr, g_xr);
  cudaGetSymbolAddress((void**)&w1t, g_w1t);
  cudaGetSymbolAddress((void**)&w2t, g_w2t);
  cudaGetSymbolAddress((void**)&wct, g_wct);

  const int SMEM_DYN = 3 * 32768;   // 98304 B -> 2 CTAs/SM
  cudaFuncSetAttribute(tc_gemm<true, true, 10>,
                       cudaFuncAttributeMaxDynamicSharedMemorySize, SMEM_DYN);
  cudaFuncSetAttribute(tc_gemm<true, true, 11>,
                       cudaFuncAttributeMaxDynamicSharedMemorySize, SMEM_DYN);
  cudaFuncSetAttribute(tc_gemm<false, false, 11>,
                       cudaFuncAttributeMaxDynamicSharedMemorySize, SMEM_DYN);

  // pre-round x; transpose+round weights into W^T (vectorized)
  {
    int n4 = (Bsz * INs) / 4;
    round_tf32_kernel<<<n4 / 256, 256>>>((const float4*)x, (float4*)xr, n4);
    transpose_round_kernel<<<dim3((Pex * INs) / 32, H1s / 128), 256>>>(
        (const float4*)W1, (float4*)w1t, Pex * INs, H1s);
    transpose_round_kernel<<<dim3((Pex * H1s) / 32, H2s / 128), 256>>>(
        (const float4*)W2, (float4*)w2t, Pex * H1s, H2s);
    transpose_round_kernel<<<dim3(H2s / 32, OUTs / 128), 256>>>(
        (const float4*)Wc, (float4*)wct, H2s, OUTs);
  }

  // ---- layer 1 ----
  selector_kernel<<<Bsz / 32, 256>>>(x, S1, sb1, p1, INs);
  tc_gemm<true, true, 10><<<dim3(H1s / 128, Bsz / 128), 128, SMEM_DYN>>>(
      H1s, Pex * INs, xr, w1t, p1, b1, h1);

  // ---- layer 2 ----
  selector_kernel<<<Bsz / 32, 256>>>(h1, S2, sb2, p2, H1s);
  tc_gemm<true, true, 11><<<dim3(H2s / 128, Bsz / 128), 128, SMEM_DYN>>>(
      H2s, Pex * H1s, h1, w2t, p2, b2, h2);

  // ---- classifier ----
  tc_gemm<false, false, 11><<<dim3(OUTs / 128, Bsz / 128), 128, SMEM_DYN>>>(
      OUTs, H2s, h2, wct, nullptr, bc, out);
}

// round 17
// speedup vs baseline: 1.0045x; 1.0007x over previous
#include <cuda_runtime.h>
#include <cstdint>

#define Bsz  8192
#define INs  1024
#define H1s  2048
#define H2s  2048
#define OUTs 1024
#define Pex  8

// Scratch (device globals: allocation-free per harness rules)
__device__ float g_h1[(size_t)Bsz * H1s];            // 64 MB (relu+tf32-rounded)
__device__ float g_h2[(size_t)Bsz * H2s];            // 64 MB (relu+tf32-rounded)
__device__ float g_p1[(size_t)Bsz * Pex];
__device__ float g_p2[(size_t)Bsz * Pex];
__device__ float g_xr[(size_t)Bsz * INs];            // 32 MB (tf32-rounded x)
__device__ float g_w1t[(size_t)H1s * Pex * INs];     // 64 MB  W1^T [H1][P*IN]
__device__ float g_w2t[(size_t)H2s * Pex * H1s];     // 128 MB W2^T [H2][P*H1]
__device__ float g_wct[(size_t)OUTs * H2s];          // 8 MB   Wc^T [OUT][H2]

// ------------------------------ helpers ---------------------------------
__device__ __forceinline__ uint32_t smem_u32(const void* p) {
  uint32_t a;
  asm("{ .reg .u64 t; cvta.to.shared.u64 t, %1; cvt.u32.u64 %0, t; }"
      : "=r"(a) : "l"(p));
  return a;
}
__device__ __forceinline__ void cpa16(uint32_t s, const void* g) {
  asm volatile("cp.async.cg.shared.global [%0], [%1], 16;" :: "r"(s), "l"(g));
}
__device__ __forceinline__ void cpa_commit() {
  asm volatile("cp.async.commit_group;" ::: "memory");
}
template <int N>
__device__ __forceinline__ void cpa_wait() {
  asm volatile("cp.async.wait_group %0;" :: "n"(N) : "memory");
}
__device__ __forceinline__ uint32_t f2tf32(float f) {
  uint32_t u;
  asm("cvt.rna.tf32.f32 %0, %1;" : "=r"(u) : "f"(f));
  return u;
}
__device__ __forceinline__ float rtf(float f) {
  return __uint_as_float(f2tf32(f));
}
__device__ __forceinline__ void ldsm4(uint32_t (&r)[4], uint32_t a) {
  asm volatile("ldmatrix.sync.aligned.m8n8.x4.shared.b16 {%0,%1,%2,%3}, [%4];"
               : "=r"(r[0]), "=r"(r[1]), "=r"(r[2]), "=r"(r[3]) : "r"(a));
}
__device__ __forceinline__ void mma_t(float (&c)[4], const uint32_t (&a)[4],
                                      uint32_t b0, uint32_t b1) {
  asm volatile(
      "mma.sync.aligned.m16n8k8.row.col.f32.tf32.tf32.f32 "
      "{%0,%1,%2,%3}, {%4,%5,%6,%7}, {%8,%9}, {%0,%1,%2,%3};"
      : "+f"(c[0]), "+f"(c[1]), "+f"(c[2]), "+f"(c[3])
      : "r"(a[0]), "r"(a[1]), "r"(a[2]), "r"(a[3]), "r"(b0), "r"(b1));
}

// -------------------------------------------------------------------------
// tf32 pre-round (x)
// -------------------------------------------------------------------------
__global__ void round_tf32_kernel(const float4* __restrict__ in,
                                  float4* __restrict__ out, int n4) {
  int i = blockIdx.x * blockDim.x + threadIdx.x;
  if (i < n4) {
    float4 v = in[i];
    v.x = rtf(v.x); v.y = rtf(v.y); v.z = rtf(v.z); v.w = rtf(v.w);
    out[i] = v;
  }
}

// -------------------------------------------------------------------------
// Vectorized transpose + tf32-round: out[n*K + k] = rna(in[k*N + n]).
// Tile 32(k) x 128(n), 256 threads, float4 gmem both sides.
// -------------------------------------------------------------------------
__global__ void transpose_round_kernel(const float4* __restrict__ in4,
                                       float4* __restrict__ out4,
                                       int K, int N) {
  __shared__ float4 t4[32][32];
  const int tid = threadIdx.x;
  const int k0 = blockIdx.x * 32, n0 = blockIdx.y * 128;
  const int N4 = N >> 2, K4 = K >> 2;

#pragma unroll
  for (int r = 0; r < 4; r++) {
    int idx = tid + r * 256;
    int k = idx >> 5, nc = idx & 31;
    t4[k][nc ^ ((k >> 2) & 7)] =
        in4[(size_t)(k0 + k) * N4 + (n0 >> 2) + nc];
  }
  __syncthreads();

  const int kb = tid & 7, nb = tid >> 3;
  float4 r0 = t4[4 * kb + 0][nb ^ kb];
  float4 r1 = t4[4 * kb + 1][nb ^ kb];
  float4 r2 = t4[4 * kb + 2][nb ^ kb];
  float4 r3 = t4[4 * kb + 3][nb ^ kb];

  size_t ob = (size_t)(n0 + 4 * nb) * K4 + (k0 >> 2) + kb;
  float4 o;
  o.x = rtf(r0.x); o.y = rtf(r1.x); o.z = rtf(r2.x); o.w = rtf(r3.x);
  out4[ob] = o;
  o.x = rtf(r0.y); o.y = rtf(r1.y); o.z = rtf(r2.y); o.w = rtf(r3.y);
  out4[ob + K4] = o;
  o.x = rtf(r0.z); o.y = rtf(r1.z); o.z = rtf(r2.z); o.w = rtf(r3.z);
  out4[ob + 2 * (size_t)K4] = o;
  o.x = rtf(r0.w); o.y = rtf(r1.w); o.z = rtf(r2.w); o.w = rtf(r3.w);
  out4[ob + 3 * (size_t)K4] = o;
}

// -------------------------------------------------------------------------
// Selector: probs = softmax(X @ S + sb). One warp per 4 rows (S reused).
// -------------------------------------------------------------------------
__global__ void selector_kernel(const float* __restrict__ X,
                                const float* __restrict__ S,
                                const float* __restrict__ sb,
                                float* __restrict__ probs, int K) {
  int gw = (blockIdx.x * blockDim.x + threadIdx.x) >> 5;
  int lane = threadIdx.x & 31;
  int row0 = gw * 4;
  int nvec = K >> 2;

  float acc[4][8];
#pragma unroll
  for (int r = 0; r < 4; r++)
#pragma unroll
    for (int p = 0; p < 8; p++) acc[r][p] = 0.f;

  for (int v = lane; v < nvec; v += 32) {
    const float4* Sv = reinterpret_cast<const float4*>(S + ((size_t)v << 2) * 8);
    float4 s0 = Sv[0], s1 = Sv[1], s2 = Sv[2], s3 = Sv[3];
    float4 s4 = Sv[4], s5 = Sv[5], s6 = Sv[6], s7 = Sv[7];
#pragma unroll
    for (int r = 0; r < 4; r++) {
      float4 x4 = reinterpret_cast<const float4*>(X + (size_t)(row0 + r) * K)[v];
      acc[r][0] += x4.x * s0.x + x4.y * s2.x + x4.z * s4.x + x4.w * s6.x;
      acc[r][1] += x4.x * s0.y + x4.y * s2.y + x4.z * s4.y + x4.w * s6.y;
      acc[r][2] += x4.x * s0.z + x4.y * s2.z + x4.z * s4.z + x4.w * s6.z;
      acc[r][3] += x4.x * s0.w + x4.y * s2.w + x4.z * s4.w + x4.w * s6.w;
      acc[r][4] += x4.x * s1.x + x4.y * s3.x + x4.z * s5.x + x4.w * s7.x;
      acc[r][5] += x4.x * s1.y + x4.y * s3.y + x4.z * s5.y + x4.w * s7.y;
      acc[r][6] += x4.x * s1.z + x4.y * s3.z + x4.z * s5.z + x4.w * s7.z;
      acc[r][7] += x4.x * s1.w + x4.y * s3.w + x4.z * s5.w + x4.w * s7.w;
    }
  }
#pragma unroll
  for (int off = 16; off; off >>= 1)
#pragma unroll
    for (int r = 0; r < 4; r++)
#pragma unroll
      for (int p = 0; p < 8; p++)
        acc[r][p] += __shfl_xor_sync(0xffffffffu, acc[r][p], off);

  if (lane < 4) {
    int r = lane;
    float a[8];
    float m = -1e30f;
#pragma unroll
    for (int p = 0; p < 8; p++) { a[p] = acc[r][p] + sb[p]; m = fmaxf(m, a[p]); }
    float s = 0.f;
#pragma unroll
    for (int p = 0; p < 8; p++) { a[p] = __expf(a[p] - m); s += a[p]; }
    float inv = 1.f / s;
#pragma unroll
    for (int p = 0; p < 8; p++) probs[(size_t)(row0 + r) * 8 + p] = a[p] * inv;
  }
}

// -------------------------------------------------------------------------
// mma.sync tf32 GEMM, CTA tile 128x128x32, 128 threads (4 warps x 64x64),
// 3-stage cp.async, 2 CTAs/SM. Both operands via ldmatrix (B = W^T).
//   MOE: probs via accumulator rescale at expert boundaries.
//   RR : relu + tf32-round at store (hidden layers).
// (FINAL: R11 configuration — measured 4424.5 / 4428.6 / 4422.8 us.)
// -------------------------------------------------------------------------
template <bool MOE, bool RR, int LOG_IN>
__global__ __launch_bounds__(128, 2) void tc_gemm(
    int N, int K,
    const float* __restrict__ X, const float* __restrict__ Wt,
    const float* __restrict__ probs, const float* __restrict__ bias,
    float* __restrict__ C) {
  constexpr int NST = 3;
  constexpr int STAGE_B = 32768;                 // A 16KB + B 16KB
  constexpr int LDA = 1 << LOG_IN;
  constexpr int MASK = LDA - 1;
  constexpr int CPE = LDA / 32;                  // chunks per expert

  extern __shared__ float smf[];
  __shared__ float probs_s[128][8];
  __shared__ float bias_s[8][128];

  const int tid = threadIdx.x, lane = tid & 31, wid = tid >> 5;
  const int wm = wid >> 1, wn = wid & 1;         // 2x2 warp grid, 64x64 tiles
  const int m0 = blockIdx.y * 128, n0 = blockIdx.x * 128;
  const uint32_t sbase = smem_u32(smf);

  if (MOE) {
    for (int i = tid; i < 1024; i += 128) {
      int r = i >> 3, p = i & 7;
      probs_s[r][p] = probs[(size_t)(m0 + r) * 8 + p];
    }
    for (int i = tid; i < 1024; i += 128) {
      int p = i >> 7, c = i & 127;
      bias_s[p][c] = bias[(size_t)p * N + n0 + c];
    }
  } else {
    bias_s[0][tid] = bias[n0 + tid];
  }

  const int nchunk = K >> 5;

  auto issue = [&](int c, int st) {
    const int k0 = c << 5;
    const uint32_t sA = sbase + (uint32_t)st * STAGE_B;
    const uint32_t sB = sA + 16384;
    const float* ab = X + (k0 & MASK);
#pragma unroll
    for (int i = 0; i < 8; i++) {            // A: 128 m-rows x 32 k, SW128
      int f = tid + i * 128;
      int m = f >> 3, g = f & 7;
      cpa16(sA + (uint32_t)(m * 128 + ((g ^ (m & 7)) << 4)),
            ab + (size_t)(m0 + m) * LDA + g * 4);
    }
#pragma unroll
    for (int i = 0; i < 8; i++) {            // B: 128 n-rows x 32 k, SW128
      int f = tid + i * 128;
      int n = f >> 3, g = f & 7;
      cpa16(sB + (uint32_t)(n * 128 + ((g ^ (n & 7)) << 4)),
            Wt + (size_t)(n0 + n) * K + k0 + g * 4);
    }
    cpa_commit();
  };

  float cacc[4][8][4];
#pragma unroll
  for (int a = 0; a < 4; a++)
#pragma unroll
    for (int b = 0; b < 8; b++)
#pragma unroll
      for (int d = 0; d < 4; d++) cacc[a][b][d] = 0.f;

  // ldmatrix per-thread address components (A: m rows; B: n rows)
  const int q = lane >> 3, r8v = lane & 7, qh = q >> 1;
  uint32_t arow[4]; int arow7[4];
#pragma unroll
  for (int mt = 0; mt < 4; mt++) {
    int r = wm * 64 + mt * 16 + (q & 1) * 8 + r8v;
    arow[mt] = (uint32_t)r * 128u;
    arow7[mt] = r & 7;
  }
  uint32_t brow[4]; int brow7[4];
#pragma unroll
  for (int nb = 0; nb < 4; nb++) {
    int r = wn * 64 + nb * 16 + (q & 1) * 8 + r8v;
    brow[nb] = (uint32_t)r * 128u;
    brow7[nb] = r & 7;
  }
  const int grp = lane >> 2, tig = lane & 3;

  float pr_lo[4], pr_hi[4];

  issue(0, 0);
  issue(1, 1);

  int st = 0;
  for (int c = 0; c < nchunk; c++) {
    cpa_wait<1>();
    __syncthreads();
    {
      int cn = c + 2;
      if (cn < nchunk) {
        int stn = st + 2; if (stn >= NST) stn -= NST;
        issue(cn, stn);
      } else {
        cpa_commit();
      }
    }

    if (MOE && (c & (CPE - 1)) == 0) {
      // expert boundary: rescale accumulator by pr_old/pr_new (registers only)
      const int p = c >> (LOG_IN - 5);
#pragma unroll
      for (int mt = 0; mt < 4; mt++) {
        int r = wm * 64 + mt * 16 + grp;
        float nlo = probs_s[r][p], nhi = probs_s[r + 8][p];
        if (c) {
          float rlo = pr_lo[mt] / nlo, rhi = pr_hi[mt] / nhi;
#pragma unroll
          for (int nt = 0; nt < 8; nt++) {
            cacc[mt][nt][0] *= rlo; cacc[mt][nt][1] *= rlo;
            cacc[mt][nt][2] *= rhi; cacc[mt][nt][3] *= rhi;
          }
        }
        pr_lo[mt] = nlo; pr_hi[mt] = nhi;
      }
    }

    const uint32_t sA = sbase + (uint32_t)st * STAGE_B;
    const uint32_t sB = sA + 16384;
#pragma unroll
    for (int ks = 0; ks < 4; ks++) {
      uint32_t af[4][4];
#pragma unroll
      for (int mt = 0; mt < 4; mt++)
        ldsm4(af[mt], sA + arow[mt] +
                          (uint32_t)(((ks * 2 + qh) ^ arow7[mt]) << 4));
      uint32_t bfr[4][4];
#pragma unroll
      for (int nb = 0; nb < 4; nb++)
        ldsm4(bfr[nb], sB + brow[nb] +
                           (uint32_t)(((ks * 2 + qh) ^ brow7[nb]) << 4));
#pragma unroll
      for (int mt = 0; mt < 4; mt++)
#pragma unroll
        for (int nb = 0; nb < 4; nb++) {
          mma_t(cacc[mt][2 * nb + 0], af[mt], bfr[nb][0], bfr[nb][2]);
          mma_t(cacc[mt][2 * nb + 1], af[mt], bfr[nb][1], bfr[nb][3]);
        }
    }
    st++; if (st >= NST) st = 0;
  }

  if (MOE) {
    // final scale by pr_last
#pragma unroll
    for (int mt = 0; mt < 4; mt++)
#pragma unroll
      for (int nt = 0; nt < 8; nt++) {
        cacc[mt][nt][0] *= pr_lo[mt]; cacc[mt][nt][1] *= pr_lo[mt];
        cacc[mt][nt][2] *= pr_hi[mt]; cacc[mt][nt][3] *= pr_hi[mt];
      }
  }

  // ---- epilogue ----
#pragma unroll
  for (int mt = 0; mt < 4; mt++) {
#pragma unroll
    for (int half = 0; half < 2; half++) {
      int r = wm * 64 + mt * 16 + grp + half * 8;
      int m = m0 + r;
      float prr[8];
      if (MOE) {
#pragma unroll
        for (int p = 0; p < 8; p++) prr[p] = probs_s[r][p];
      }
#pragma unroll
      for (int nt = 0; nt < 8; nt++) {
        int nloc = wn * 64 + nt * 8 + tig * 2;
        float v0 = cacc[mt][nt][half * 2 + 0];
        float v1 = cacc[mt][nt][half * 2 + 1];
        if (MOE) {
          float cb0 = 0.f, cb1 = 0.f;
#pragma unroll
          for (int p = 0; p < 8; p++) {
            cb0 += prr[p] * bias_s[p][nloc];
            cb1 += prr[p] * bias_s[p][nloc + 1];
          }
          v0 += cb0; v1 += cb1;
        } else {
          v0 += bias_s[0][nloc];
          v1 += bias_s[0][nloc + 1];
        }
        if (RR) {
          v0 = rtf(fmaxf(v0, 0.f));
          v1 = rtf(fmaxf(v1, 0.f));
        }
        float2 o; o.x = v0; o.y = v1;
        *reinterpret_cast<float2*>(&C[(size_t)m * N + n0 + nloc]) = o;
      }
    }
  }
}

// -------------------------------------------------------------------------
extern "C" void kernel_launch(void* const* d_in, const int* in_sizes, int n_in,
                              void* d_out, int out_size) {
  const float* x   = (const float*)d_in[0];
  const float* W1  = (const float*)d_in[1];
  const float* b1  = (const float*)d_in[2];
  const float* S1  = (const float*)d_in[3];
  const float* sb1 = (const float*)d_in[4];
  const float* W2  = (const float*)d_in[5];
  const float* b2  = (const float*)d_in[6];
  const float* S2  = (const float*)d_in[7];
  const float* sb2 = (const float*)d_in[8];
  const float* Wc  = (const float*)d_in[9];
  const float* bc  = (const float*)d_in[10];
  float* out = (float*)d_out;

  float *h1, *h2, *p1, *p2, *xr, *w1t, *w2t, *wct;
  cudaGetSymbolAddress((void**)&h1, g_h1);
  cudaGetSymbolAddress((void**)&h2, g_h2);
  cudaGetSymbolAddress((void**)&p1, g_p1);
  cudaGetSymbolAddress((void**)&p2, g_p2);
  cudaGetSymbolAddress((void**)&xr, g_xr);
  cudaGetSymbolAddress((void**)&w1t, g_w1t);
  cudaGetSymbolAddress((void**)&w2t, g_w2t);
  cudaGetSymbolAddress((void**)&wct, g_wct);

  const int SMEM_DYN = 3 * 32768;   // 98304 B -> 2 CTAs/SM
  cudaFuncSetAttribute(tc_gemm<true, true, 10>,
                       cudaFuncAttributeMaxDynamicSharedMemorySize, SMEM_DYN);
  cudaFuncSetAttribute(tc_gemm<true, true, 11>,
                       cudaFuncAttributeMaxDynamicSharedMemorySize, SMEM_DYN);
  cudaFuncSetAttribute(tc_gemm<false, false, 11>,
                       cudaFuncAttributeMaxDynamicSharedMemorySize, SMEM_DYN);

  // pre-round x; transpose+round weights into W^T (vectorized)
  {
    int n4 = (Bsz * INs) / 4;
    round_tf32_kernel<<<n4 / 256, 256>>>((const float4*)x, (float4*)xr, n4);
    transpose_round_kernel<<<dim3((Pex * INs) / 32, H1s / 128), 256>>>(
        (const float4*)W1, (float4*)w1t, Pex * INs, H1s);
    transpose_round_kernel<<<dim3((Pex * H1s) / 32, H2s / 128), 256>>>(
        (const float4*)W2, (float4*)w2t, Pex * H1s, H2s);
    transpose_round_kernel<<<dim3(H2s / 32, OUTs / 128), 256>>>(
        (const float4*)Wc, (float4*)wct, H2s, OUTs);
  }

  // ---- layer 1 ----
  selector_kernel<<<Bsz / 32, 256>>>(x, S1, sb1, p1, INs);
  tc_gemm<true, true, 10><<<dim3(H1s / 128, Bsz / 128), 128, SMEM_DYN>>>(
      H1s, Pex * INs, xr, w1t, p1, b1, h1);

  // ---- layer 2 ----
  selector_kernel<<<Bsz / 32, 256>>>(h1, S2, sb2, p2, H1s);
  tc_gemm<true, true, 11><<<dim3(H2s / 128, Bsz / 128), 128, SMEM_DYN>>>(
      H2s, Pex * H1s, h1, w2t, p2, b2, h2);

  // ---- classifier ----
  tc_gemm<false, false, 11><<<dim3(OUTs / 128, Bsz / 128), 128, SMEM_DYN>>>(
      OUTs, H2s, h2, wct, nullptr, bc, out);
}